// round 6
// baseline (speedup 1.0000x reference)
#include <cuda_runtime.h>
#include <cstdint>

#define NTH 512
// smem float offsets
#define RBFP_O 0        // 2048 float4  (A-packed rbf, K=64)
#define A1P_O  8192     // 4096 float4  (A-packed a1, K=128)
#define BRAW_O 24576    // raw staged weight tile [64][136]
#define BP0_O  33280    // 2048 float4 packed B
#define BP1_O  41472    // 2048 float4 packed B
#define PB_O   49664    // 7*128 per-feature params
#define WFS_O  50560    // softmax(att)
#define LNB_O  50624    // float2[128][2]
#define HB_O   51136    // head exchange 256*9
#define SMF    53440

__device__ __forceinline__ void cpa16(uint32_t dst, const void* src){
  asm volatile("cp.async.cg.shared.global [%0], [%1], 16;"::"r"(dst),"l"(src):"memory");
}
#define CPCOMMIT() asm volatile("cp.async.commit_group;":::"memory")
#define CPWAIT0()  asm volatile("cp.async.wait_group 0;":::"memory")
__device__ __forceinline__ uint32_t s2u(const void* p){
  uint32_t a;
  asm("{.reg .u64 t; cvta.to.shared.u64 t,%1; cvt.u32.u64 %0,t;}":"=r"(a):"l"(p));
  return a;
}
__device__ __forceinline__ void mma8(float (&d)[4],
                                     uint32_t a0, uint32_t a1, uint32_t a2, uint32_t a3,
                                     uint32_t b0, uint32_t b1){
  asm("mma.sync.aligned.m16n8k8.row.col.f32.tf32.tf32.f32 "
      "{%0,%1,%2,%3},{%4,%5,%6,%7},{%8,%9},{%0,%1,%2,%3};"
      : "+f"(d[0]), "+f"(d[1]), "+f"(d[2]), "+f"(d[3])
      : "r"(a0), "r"(a1), "r"(a2), "r"(a3), "r"(b0), "r"(b1));
}
__device__ __forceinline__ float clampf(float v,float lo,float hi){return fminf(fmaxf(v,lo),hi);}
__device__ __forceinline__ float gelu_f(float x){
  float u = x*(0.7978845608f + 0.035677408f*x*x);
  float t; asm("tanh.approx.f32 %0, %1;":"=f"(t):"f"(u));
  return 0.5f*x*(1.0f+t);
}
__device__ __forceinline__ float softplus_f(float x){return (x>15.0f)?x:log1pf(expf(x));}
__device__ __forceinline__ float quad_sum(float v){
  v += __shfl_xor_sync(0xffffffffu, v, 1);
  v += __shfl_xor_sync(0xffffffffu, v, 2);
  return v;
}

// ---- packed GEMM: 1 LDS.128 (A) + 4 LDS.128 (B) + 8 MMA per k-step ----
template<int KSTEPS>
__device__ __forceinline__ void gemm_packed(float (&acc)[8][4],
    const float4* __restrict__ Ap4, int kA0blk,
    const float4* __restrict__ Bp4,
    int wr, int wc, int innerA)
{
#pragma unroll
  for(int ks=0; ks<KSTEPS; ++ks){
    float4 av = Ap4[((((kA0blk+ks)<<3)+wr)<<5) + innerA];
    uint32_t a0=__float_as_uint(av.x), a1=__float_as_uint(av.y),
             a2=__float_as_uint(av.z), a3=__float_as_uint(av.w);
#pragma unroll
    for(int p=0;p<4;++p){
      float4 bv = Bp4[(((ks<<3)+(p<<1)+wc)<<5) + innerA];
      mma8(acc[2*p],   a0,a1,a2,a3, __float_as_uint(bv.x), __float_as_uint(bv.y));
      mma8(acc[2*p+1], a0,a1,a2,a3, __float_as_uint(bv.z), __float_as_uint(bv.w));
    }
  }
}

// cp.async raw stage: W[64][128] row-major -> braw[64][136]
__device__ __forceinline__ void stage_raw(uint32_t brawu, const float* __restrict__ W, int tid){
  int n4 = (tid & 31) << 2;
  int k0 = tid >> 5;
#pragma unroll
  for(int i=0;i<4;++i){
    int k = k0 + i*16;
    cpa16(brawu + (uint32_t)(k*136 + n4)*4u, W + k*128 + n4);
  }
}

// repack braw[64][136] -> packed B (2048 float4). Conflict-free both sides.
__device__ __forceinline__ void repack(float4* __restrict__ bp4,
                                       const float* __restrict__ braw, int tid){
#pragma unroll
  for(int i=0;i<4;++i){
    int id = tid + i*NTH;
    int inner = id & 31;
    int t = inner & 3;
    int g = ((inner>>3)<<1) | ((inner>>2)&1);
    int mid = (id>>5)&7;
    int wc = mid&1, p = mid>>1;
    int kb = id>>8;
    int n = wc*64 + p*16 + g;
    int k = kb*8 + t;
    float4 v;
    v.x = braw[k*136 + n];
    v.y = braw[(k+4)*136 + n];
    v.z = braw[k*136 + n + 8];
    v.w = braw[(k+4)*136 + n + 8];
    bp4[((id>>5)<<5) + inner] = v;
  }
}

__global__ void __launch_bounds__(NTH, 1)
nam_pk_kernel(const float* __restrict__ x,const float* __restrict__ centers,
              const float* __restrict__ logw,
              const float* __restrict__ W1,const float* __restrict__ b1,
              const float* __restrict__ g1,const float* __restrict__ be1,
              const float* __restrict__ W2,const float* __restrict__ b2,
              const float* __restrict__ g2,const float* __restrict__ be2,
              const float* __restrict__ Wr,const float* __restrict__ br,
              const float* __restrict__ att,const float* __restrict__ bias,
              const float* __restrict__ Wpi,const float* __restrict__ bpi,
              const float* __restrict__ Wa,const float* __restrict__ ba,
              const float* __restrict__ Wb,const float* __restrict__ bb,
              float* __restrict__ out)
{
  extern __shared__ float sm[];
  float4* rbfp4 = (float4*)(sm + RBFP_O);
  float4* a1p4  = (float4*)(sm + A1P_O);
  float*  braw  = sm + BRAW_O;
  float4* bp0   = (float4*)(sm + BP0_O);
  float4* bp1   = (float4*)(sm + BP1_O);
  float*  pbf   = sm + PB_O;
  float*  wfs   = sm + WFS_O;
  float2* lnb   = (float2*)(sm + LNB_O);
  float*  hb    = sm + HB_O;
  const uint32_t brawu = s2u(braw);

  const int tid = threadIdx.x;
  const int w = tid >> 5, lane = tid & 31;
  const int g = lane >> 2, t = lane & 3;
  const int wr = w >> 1, wc = w & 1;
  const int rA0 = wr*16 + g;           // rows rA0, rA0+8
  const int innerA = ((g>>1)<<3) | ((g&1)<<2) | t;
  const int b0 = blockIdx.x * 128;

  if(tid == 0){
    float mx = -3.4e38f;
    for(int i=0;i<64;++i) mx = fmaxf(mx, att[i]);
    float s = 0.f;
    for(int i=0;i<64;++i){ float e = expf(att[i]-mx); wfs[i] = e; s += e; }
    float inv = 1.f/s;
    for(int i=0;i<64;++i) wfs[i] *= inv;
  }

  // prologue: W1(f0) -> braw
  stage_raw(brawu, W1, tid); CPCOMMIT();

  float agg[2][16];
#pragma unroll
  for(int r2=0;r2<2;++r2)
#pragma unroll
    for(int j=0;j<16;++j) agg[r2][j] = 0.f;

  for(int f=0; f<64; ++f){
    const int fn = (f+1) & 63;
    __syncthreads();  // S0: prev iter fully done

    // ---- seg0: RBF -> packed A slots; params -> pb ----
#pragma unroll
    for(int i=0;i<4;++i){
      int id = tid + i*NTH;
      int inner = id & 31;
      int tt = inner & 3;
      int gg = ((inner>>3)<<1) | ((inner>>2)&1);
      int wrr = (id>>5)&7;
      int kb = id>>8;
      int r = wrr*16 + gg;
      int k = kb*8 + tt;
      float x0 = clampf(x[(b0+r)*64 + f],   -10.f, 10.f);
      float x1 = clampf(x[(b0+r+8)*64 + f], -10.f, 10.f);
      float cA = centers[f*64 + k],   cB = centers[f*64 + k + 4];
      float wA = __expf(clampf(logw[f*64 + k],   -5.f, 5.f)) + 0.1f;
      float wB = __expf(clampf(logw[f*64 + k+4], -5.f, 5.f)) + 0.1f;
      float4 v;
      { float d=clampf(__fdividef(x0-cA,wA),-10.f,10.f); v.x=__expf(-0.5f*d*d); }
      { float d=clampf(__fdividef(x1-cA,wA),-10.f,10.f); v.y=__expf(-0.5f*d*d); }
      { float d=clampf(__fdividef(x0-cB,wB),-10.f,10.f); v.z=__expf(-0.5f*d*d); }
      { float d=clampf(__fdividef(x1-cB,wB),-10.f,10.f); v.w=__expf(-0.5f*d*d); }
      rbfp4[((id>>5)<<5) + inner] = v;
    }
    for(int i=tid; i<896; i+=NTH){
      int seg = i >> 7, c = i & 127;
      const float* sp = (seg==0)?b1:(seg==1)?g1:(seg==2)?be1:(seg==3)?b2:(seg==4)?g2:(seg==5)?be2:br;
      pbf[i] = sp[f*128 + c];
    }
    CPWAIT0(); __syncthreads();    // S1: braw=W1; rbf/pb visible

    repack(bp0, braw, tid);        // seg1: W1 -> bp0
    __syncthreads();               // S2: bp0 ready; braw free

    // seg2: stage W2a; GEMM1; LN1 stats
    stage_raw(brawu, W2 + (size_t)f*16384, tid); CPCOMMIT();
    float acc[8][4];
#pragma unroll
    for(int j=0;j<8;++j){ acc[j][0]=acc[j][1]=acc[j][2]=acc[j][3]=0.f; }
    gemm_packed<8>(acc, rbfp4, 0, bp0, wr, wc, innerA);
    {
      float s0=0.f,q0=0.f,s1=0.f,q1=0.f;
#pragma unroll
      for(int j=0;j<8;++j){
        int col = wc*64 + j*8 + t*2;
        float2 bv = *(const float2*)&pbf[col];
        float v0=acc[j][0]+bv.x, v1=acc[j][1]+bv.y;
        float v2=acc[j][2]+bv.x, v3=acc[j][3]+bv.y;
        s0+=v0+v1; q0+=v0*v0+v1*v1;
        s1+=v2+v3; q1+=v2*v2+v3*v3;
      }
      s0=quad_sum(s0); q0=quad_sum(q0); s1=quad_sum(s1); q1=quad_sum(q1);
      if(t==0){
        lnb[rA0*2 + wc]     = make_float2(s0,q0);
        lnb[(rA0+8)*2 + wc] = make_float2(s1,q1);
      }
    }
    CPWAIT0(); __syncthreads();    // S3: braw=W2a; lnb visible

    // seg3: repack W2a -> bp1; epilogue1 -> packed a1
    repack(bp1, braw, tid);
    {
      float2 pA0 = lnb[rA0*2 + wc],     pB0 = lnb[rA0*2 + (wc^1)];
      float2 pA1 = lnb[(rA0+8)*2 + wc], pB1 = lnb[(rA0+8)*2 + (wc^1)];
      float mu0=(pA0.x+pB0.x)*(1.f/128.f);
      float rs0=rsqrtf((pA0.y+pB0.y)*(1.f/128.f)-mu0*mu0+1e-5f);
      float mu1=(pA1.x+pB1.x)*(1.f/128.f);
      float rs1=rsqrtf((pA1.y+pB1.y)*(1.f/128.f)-mu1*mu1+1e-5f);
#pragma unroll
      for(int j=0;j<8;++j){
        int col = wc*64 + j*8 + t*2;
        float2 bv = *(const float2*)&pbf[col];
        float2 gv = *(const float2*)&pbf[128+col];
        float2 ev = *(const float2*)&pbf[256+col];
        float v0 = gelu_f((acc[j][0]+bv.x-mu0)*rs0*gv.x+ev.x);
        float v1 = gelu_f((acc[j][1]+bv.y-mu0)*rs0*gv.y+ev.y);
        float v2 = gelu_f((acc[j][2]+bv.x-mu1)*rs1*gv.x+ev.x);
        float v3 = gelu_f((acc[j][3]+bv.y-mu1)*rs1*gv.y+ev.y);
        // packed-A store: col c -> (kbc, t', h); pairs {row, row+8}
#pragma unroll
        for(int cc=0; cc<2; ++cc){
          int c = col + cc;
          int kbc = (c>>3);                 // = wc*8 + j
          int tp = c & 3;
          int h  = (c>>2) & 1;
          int slot = ((kbc<<3) + wr)*32 + ((g>>1)<<3) + ((g&1)<<2) + tp;
          float2 pr = cc ? make_float2(v1,v3) : make_float2(v0,v2);
          *(float2*)((float*)a1p4 + slot*4 + h*2) = pr;
        }
      }
    }
    __syncthreads();               // S4: a1p + bp1 ready; braw free

    // seg4: stage W2b; GEMM2a
    stage_raw(brawu, W2 + (size_t)f*16384 + 64*128, tid); CPCOMMIT();
    float acc2[8][4];
#pragma unroll
    for(int j=0;j<8;++j){ acc2[j][0]=acc2[j][1]=acc2[j][2]=acc2[j][3]=0.f; }
    gemm_packed<8>(acc2, a1p4, 0, bp1, wr, wc, innerA);
    CPWAIT0(); __syncthreads();    // S5: braw=W2b; bp0 free

    repack(bp0, braw, tid);        // seg5: W2b -> bp0
    __syncthreads();               // S6: bp0 ready; braw free

    // seg6: stage Wr; GEMM2b; LN2 stats
    stage_raw(brawu, Wr + (size_t)f*8192, tid); CPCOMMIT();
    gemm_packed<8>(acc2, a1p4, 8, bp0, wr, wc, innerA);
    {
      float s0=0.f,q0=0.f,s1=0.f,q1=0.f;
#pragma unroll
      for(int j=0;j<8;++j){
        int col = wc*64 + j*8 + t*2;
        float2 bv = *(const float2*)&pbf[384+col];
        float v0=acc2[j][0]+bv.x, v1=acc2[j][1]+bv.y;
        float v2=acc2[j][2]+bv.x, v3=acc2[j][3]+bv.y;
        s0+=v0+v1; q0+=v0*v0+v1*v1;
        s1+=v2+v3; q1+=v2*v2+v3*v3;
      }
      s0=quad_sum(s0); q0=quad_sum(q0); s1=quad_sum(s1); q1=quad_sum(q1);
      if(t==0){
        lnb[rA0*2 + wc]     = make_float2(s0,q0);
        lnb[(rA0+8)*2 + wc] = make_float2(s1,q1);
      }
    }
    CPWAIT0(); __syncthreads();    // S7: braw=Wr; lnb visible; bp1 free

    // seg7: repack Wr -> bp1; epilogue2 -> agg
    repack(bp1, braw, tid);
    const float wf = wfs[f];
    {
      float2 pA0 = lnb[rA0*2 + wc],     pB0 = lnb[rA0*2 + (wc^1)];
      float2 pA1 = lnb[(rA0+8)*2 + wc], pB1 = lnb[(rA0+8)*2 + (wc^1)];
      float mu0=(pA0.x+pB0.x)*(1.f/128.f);
      float rs0=rsqrtf((pA0.y+pB0.y)*(1.f/128.f)-mu0*mu0+1e-5f);
      float mu1=(pA1.x+pB1.x)*(1.f/128.f);
      float rs1=rsqrtf((pA1.y+pB1.y)*(1.f/128.f)-mu1*mu1+1e-5f);
#pragma unroll
      for(int j=0;j<8;++j){
        int col = wc*64 + j*8 + t*2;
        float2 bv = *(const float2*)&pbf[384+col];
        float2 gv = *(const float2*)&pbf[512+col];
        float2 ev = *(const float2*)&pbf[640+col];
        agg[0][j*2]   += wf*gelu_f((acc2[j][0]+bv.x-mu0)*rs0*gv.x+ev.x);
        agg[0][j*2+1] += wf*gelu_f((acc2[j][1]+bv.y-mu0)*rs0*gv.y+ev.y);
        agg[1][j*2]   += wf*gelu_f((acc2[j][2]+bv.x-mu1)*rs1*gv.x+ev.x);
        agg[1][j*2+1] += wf*gelu_f((acc2[j][3]+bv.y-mu1)*rs1*gv.y+ev.y);
      }
    }
    __syncthreads();               // S8: bp1 ready; braw free

    // seg8: stage W1(next); GEMMr; residual agg
    stage_raw(brawu, W1 + (size_t)fn*8192, tid); CPCOMMIT();
    float accr[8][4];
#pragma unroll
    for(int j=0;j<8;++j){ accr[j][0]=accr[j][1]=accr[j][2]=accr[j][3]=0.f; }
    gemm_packed<8>(accr, rbfp4, 0, bp1, wr, wc, innerA);
    {
      const float cr = 0.1f*wf;
#pragma unroll
      for(int j=0;j<8;++j){
        int col = wc*64 + j*8 + t*2;
        float2 bv = *(const float2*)&pbf[768+col];
        agg[0][j*2]   += cr*(accr[j][0]+bv.x);
        agg[0][j*2+1] += cr*(accr[j][1]+bv.y);
        agg[1][j*2]   += cr*(accr[j][2]+bv.x);
        agg[1][j*2+1] += cr*(accr[j][3]+bv.y);
      }
    }
  }

  // ---- mixture-beta head ----
  float p[2][9];
#pragma unroll
  for(int r2=0;r2<2;++r2)
#pragma unroll
    for(int q=0;q<9;++q) p[r2][q]=0.f;
#pragma unroll
  for(int j=0;j<8;++j){
#pragma unroll
    for(int cc=0;cc<2;++cc){
      int c = wc*64 + j*8 + t*2 + cc;
      float bs = __ldg(&bias[c]);
      float av0 = agg[0][j*2+cc] + bs;
      float av1 = agg[1][j*2+cc] + bs;
#pragma unroll
      for(int q=0;q<3;++q){
        float wp=__ldg(&Wpi[c*3+q]);
        float wa=__ldg(&Wa[c*3+q]);
        float wb=__ldg(&Wb[c*3+q]);
        p[0][q]+=av0*wp;   p[1][q]+=av1*wp;
        p[0][3+q]+=av0*wa; p[1][3+q]+=av1*wa;
        p[0][6+q]+=av0*wb; p[1][6+q]+=av1*wb;
      }
    }
  }
#pragma unroll
  for(int r2=0;r2<2;++r2)
#pragma unroll
    for(int q=0;q<9;++q) p[r2][q]=quad_sum(p[r2][q]);

  __syncthreads();
  if(t==0){
#pragma unroll
    for(int q=0;q<9;++q){
      hb[(wc*128 + rA0)*9 + q]     = p[0][q];
      hb[(wc*128 + rA0 + 8)*9 + q] = p[1][q];
    }
  }
  __syncthreads();

  if(wc==0 && t==0){
#pragma unroll
    for(int rr=0;rr<2;++rr){
      int r = rA0 + rr*8;
      float z[9];
#pragma unroll
      for(int q=0;q<9;++q) z[q] = hb[r*9+q] + hb[(128+r)*9+q];
      float p0=z[0]+bpi[0], p1=z[1]+bpi[1], p2=z[2]+bpi[2];
      float m=fmaxf(p0,fmaxf(p1,p2));
      float e0=expf(p0-m), e1=expf(p1-m), e2=expf(p2-m);
      float al0=clampf(softplus_f(z[3]+ba[0])+1.01f,1.01f,100.f);
      float al1=clampf(softplus_f(z[4]+ba[1])+1.01f,1.01f,100.f);
      float al2=clampf(softplus_f(z[5]+ba[2])+1.01f,1.01f,100.f);
      float bt0=clampf(softplus_f(z[6]+bb[0])+1.01f,1.01f,100.f);
      float bt1=clampf(softplus_f(z[7]+bb[1])+1.01f,1.01f,100.f);
      float bt2=clampf(softplus_f(z[8]+bb[2])+1.01f,1.01f,100.f);
      float pred=e0*al0/(al0+bt0)+e1*al1/(al1+bt1)+e2*al2/(al2+bt2);
      pred/=(e0+e1+e2);
      out[b0+r]=clampf(pred,0.001f,0.999f);
    }
  }
}

extern "C" void kernel_launch(void* const* d_in,const int* in_sizes,int n_in,
                              void* d_out,int out_size)
{
  const float* x=(const float*)d_in[0];
  const float* centers=(const float*)d_in[1];
  const float* logw=(const float*)d_in[2];
  const float* W1=(const float*)d_in[3];
  const float* b1=(const float*)d_in[4];
  const float* g1=(const float*)d_in[5];
  const float* be1=(const float*)d_in[6];
  const float* W2=(const float*)d_in[7];
  const float* b2=(const float*)d_in[8];
  const float* g2=(const float*)d_in[9];
  const float* be2=(const float*)d_in[10];
  const float* Wr=(const float*)d_in[11];
  const float* br=(const float*)d_in[12];
  const float* att=(const float*)d_in[13];
  const float* bias=(const float*)d_in[14];
  const float* Wpi=(const float*)d_in[15];
  const float* bpi=(const float*)d_in[16];
  const float* Wa=(const float*)d_in[17];
  const float* ba=(const float*)d_in[18];
  const float* Wb=(const float*)d_in[19];
  const float* bb=(const float*)d_in[20];
  float* out=(float*)d_out;

  const int smem_bytes = SMF*4;   // 213760 B
  cudaFuncSetAttribute(nam_pk_kernel,cudaFuncAttributeMaxDynamicSharedMemorySize,smem_bytes);
  nam_pk_kernel<<<128,NTH,smem_bytes>>>(x,centers,logw,W1,b1,g1,be1,W2,b2,g2,be2,
                                        Wr,br,att,bias,Wpi,bpi,Wa,ba,Wb,bb,out);
}